// round 14
// baseline (speedup 1.0000x reference)
#include <cuda_runtime.h>
#include <cuda_fp16.h>
#include <math.h>
#include <stdint.h>

#define NTOK 4096
#define DIM  1024
#define HDIM 4096
#define NEXP 8
#define NPAIR (NTOK * 2)

#define BM 128
#define BN 256
#define STAGES 3
#define TILE_B 16384             // A tile: 128 rows x 128 bytes
#define BTILE_B 32768            // B tile: 256 rows x 128 bytes
#define STAGE_B (2 * TILE_B + BTILE_B)   // Ah, Al, B = 64 KB
#define GEMM_SMEM (STAGES * STAGE_B)     // 192 KB
#define NTHR 512

// ---------------- scratch (static device globals; no runtime allocation) ----
__device__ __half g_x_hi[(size_t)NTOK * DIM];
__device__ __half g_x_lo[(size_t)NTOK * DIM];
__device__ __half g_xg_hi[(size_t)NPAIR * DIM];
__device__ __half g_xg_lo[(size_t)NPAIR * DIM];
__device__ __half g_wupT[(size_t)NEXP * HDIM * DIM];  // [e][h][d] fp16
__device__ __half g_wdnT[(size_t)NEXP * DIM * HDIM];  // [e][d][h] fp16
__device__ __half g_wsuT[(size_t)HDIM * DIM];
__device__ __half g_wsdT[(size_t)DIM * HDIM];
__device__ __half g_hsh_hi[(size_t)NTOK * HDIM];
__device__ __half g_hsh_lo[(size_t)NTOK * HDIM];
__device__ __half g_hrt_hi[(size_t)NPAIR * HDIM];
__device__ __half g_hrt_lo[(size_t)NPAIR * HDIM];
__device__ float g_pair_out[(size_t)NPAIR * DIM];
__device__ float g_pair_prob[NPAIR];
__device__ int   g_pair_token[NPAIR];
__device__ int   g_pair_pos[NPAIR];
__device__ int   g_topk_idx[NPAIR];
__device__ float g_topk_p[NPAIR];
__device__ int   g_counts[NEXP];
__device__ int   g_offsets[NEXP];
__device__ int   g_cursor[NEXP];

// ---------------- PTX helpers (sm_80-era only: valid on plain sm_103) -------
__device__ __forceinline__ uint32_t smem_u32(const void* p) {
    return (uint32_t)__cvta_generic_to_shared(p);
}
#define CP_ASYNC(dst, src, sz) \
    asm volatile("cp.async.cg.shared.global [%0], [%1], 16, %2;" \
                 :: "r"(dst), "l"(src), "r"(sz) : "memory")
#define CP_COMMIT() asm volatile("cp.async.commit_group;" ::: "memory")
#define CP_WAIT(n)  asm volatile("cp.async.wait_group %0;" :: "n"(n) : "memory")
#define LDSM4(r, a) \
    asm volatile("ldmatrix.sync.aligned.m8n8.x4.shared.b16 {%0,%1,%2,%3}, [%4];" \
                 : "=r"((r)[0]), "=r"((r)[1]), "=r"((r)[2]), "=r"((r)[3]) : "r"(a))
#define MMA16816(c, a, b0, b1) \
    asm volatile("mma.sync.aligned.m16n8k16.row.col.f32.f16.f16.f32 " \
                 "{%0,%1,%2,%3},{%4,%5,%6,%7},{%8,%9},{%0,%1,%2,%3};" \
                 : "+f"((c)[0]), "+f"((c)[1]), "+f"((c)[2]), "+f"((c)[3]) \
                 : "r"((a)[0]), "r"((a)[1]), "r"((a)[2]), "r"((a)[3]), \
                   "r"(b0), "r"(b1))

__device__ __forceinline__ uint32_t pack_half2(float a, float b) {
    __half h0 = __float2half_rn(a);
    __half h1 = __float2half_rn(b);
    return (uint32_t)__half_as_ushort(h0) | ((uint32_t)__half_as_ushort(h1) << 16);
}

// ---------------- tiny kernels ----------------------------------------------
__global__ void zero_counts_kernel() {
    if (threadIdx.x < NEXP) g_counts[threadIdx.x] = 0;
}

__global__ void router_kernel(const float* __restrict__ x,
                              const float* __restrict__ Wr) {
    int gw   = (blockIdx.x * blockDim.x + threadIdx.x) >> 5;
    int lane = threadIdx.x & 31;
    if (gw >= NTOK) return;
    const float* xr = x + (size_t)gw * DIM;
    float acc[NEXP];
#pragma unroll
    for (int e = 0; e < NEXP; e++) acc[e] = 0.f;
    for (int d = lane; d < DIM; d += 32) {
        float xv = xr[d];
        const float* w = Wr + (size_t)d * NEXP;
#pragma unroll
        for (int e = 0; e < NEXP; e++) acc[e] += xv * w[e];
    }
#pragma unroll
    for (int off = 16; off > 0; off >>= 1) {
#pragma unroll
        for (int e = 0; e < NEXP; e++)
            acc[e] += __shfl_xor_sync(0xffffffffu, acc[e], off);
    }
    if (lane == 0) {
        float p[NEXP];
#pragma unroll
        for (int e = 0; e < NEXP; e++) p[e] = 1.f / (1.f + expf(-acc[e]));
        float p1 = -1.f, p2 = -1.f; int i1 = 0, i2 = 0;
#pragma unroll
        for (int e = 0; e < NEXP; e++) {
            float v = p[e];
            if (v > p1)      { p2 = p1; i2 = i1; p1 = v; i1 = e; }
            else if (v > p2) { p2 = v;  i2 = e; }
        }
        float s = p1 + p2 + 1e-6f;
        p1 /= s; p2 /= s;
        g_topk_idx[2 * gw]     = i1;  g_topk_idx[2 * gw + 1] = i2;
        g_topk_p[2 * gw]       = p1;  g_topk_p[2 * gw + 1]   = p2;
        atomicAdd(&g_counts[i1], 1);
        atomicAdd(&g_counts[i2], 1);
    }
}

__global__ void prefix_kernel() {
    if (threadIdx.x == 0) {
        int s = 0;
        for (int e = 0; e < NEXP; e++) {
            g_offsets[e] = s; g_cursor[e] = s; s += g_counts[e];
        }
    }
}

__global__ void scatter_kernel() {
    int n = blockIdx.x * blockDim.x + threadIdx.x;
    if (n >= NTOK) return;
#pragma unroll
    for (int j = 0; j < 2; j++) {
        int e = g_topk_idx[2 * n + j];
        int pos = atomicAdd(&g_cursor[e], 1);
        g_pair_token[pos] = n;
        g_pair_prob[pos]  = g_topk_p[2 * n + j];
        g_pair_pos[2 * n + j] = pos;
    }
}

// split x -> fp16 hi/lo
__global__ void split_x_kernel(const float* __restrict__ x) {
    size_t i = ((size_t)blockIdx.x * blockDim.x + threadIdx.x) * 4;
    float4 v = *(const float4*)(x + i);
    float f[4] = {v.x, v.y, v.z, v.w};
    uint32_t hi[2], lo[2];
#pragma unroll
    for (int p = 0; p < 2; p++) {
        __half h0 = __float2half_rn(f[2 * p]);
        __half h1 = __float2half_rn(f[2 * p + 1]);
        float l0 = f[2 * p]     - __half2float(h0);
        float l1 = f[2 * p + 1] - __half2float(h1);
        hi[p] = (uint32_t)__half_as_ushort(h0) | ((uint32_t)__half_as_ushort(h1) << 16);
        lo[p] = pack_half2(l0, l1);
    }
    *(uint2*)(g_x_hi + i) = make_uint2(hi[0], hi[1]);
    *(uint2*)(g_x_lo + i) = make_uint2(lo[0], lo[1]);
}

__global__ void gather_x_kernel() {
    int pos = blockIdx.x;
    int tok = g_pair_token[pos];
    int d = threadIdx.x;  // 128 threads x 8 fp16
    ((uint4*)(g_xg_hi + (size_t)pos * DIM))[d] =
        ((const uint4*)(g_x_hi + (size_t)tok * DIM))[d];
    ((uint4*)(g_xg_lo + (size_t)pos * DIM))[d] =
        ((const uint4*)(g_x_lo + (size_t)tok * DIM))[d];
}

// transpose [R,C] fp32 -> [C,R] fp16  (blockIdx.z = expert slab)
__global__ void transpose_half_kernel(const float* __restrict__ src,
                                      __half* __restrict__ dst,
                                      int R, int C) {
    __shared__ float tile[32][33];
    size_t eo = (size_t)blockIdx.z * R * C;
    int c0 = blockIdx.x * 32, r0 = blockIdx.y * 32;
    int tx = threadIdx.x, ty = threadIdx.y;
#pragma unroll
    for (int i = 0; i < 4; i++)
        tile[ty + 8 * i][tx] = src[eo + (size_t)(r0 + ty + 8 * i) * C + c0 + tx];
    __syncthreads();
#pragma unroll
    for (int i = 0; i < 4; i++) {
        float v = tile[tx][ty + 8 * i];
        dst[eo + (size_t)(c0 + ty + 8 * i) * R + r0 + tx] = __float2half_rn(v);
    }
}

// ---------------- HMMA fp16x2 GEMM (128x256 tile, 16 warps 4x4, wtile 32x64) -
// C = A@B^T. A K-major fp16 hi/lo (exact to 2^-22), B fp16 single.
// 2 MMA products per fragment. cp.async 3-stage pipeline, XOR-swizzled smem.
// blockIdx.z: 0..NEXP-1 routed experts, NEXP = shared expert.

__device__ __forceinline__ void load_stage(uint32_t sbase,
    const char* Ah, const char* Al, const char* B,
    size_t rowB, size_t kb, int rmax, int tid) {
    // A tiles: 128 rows x 8 16B-chunks = 1024 cps per tile
#pragma unroll
    for (int t = 0; t < 2; t++) {
        int id = tid + t * NTHR;
        int r = id >> 3, c = id & 7;
        uint32_t dst = sbase + (uint32_t)(r * 128 + ((c ^ (r & 7)) << 4));
        size_t go = (size_t)r * rowB + kb + (size_t)(c << 4);
        int av = (r < rmax);
        size_t ga = av ? go : 0;
        int sz = av ? 16 : 0;
        CP_ASYNC(dst,          Ah + ga, sz);
        CP_ASYNC(dst + TILE_B, Al + ga, sz);
    }
    // B tile: 256 rows x 8 chunks = 2048 cps
#pragma unroll
    for (int t = 0; t < 4; t++) {
        int id = tid + t * NTHR;
        int r = id >> 3, c = id & 7;
        uint32_t dst = sbase + 2 * TILE_B + (uint32_t)(r * 128 + ((c ^ (r & 7)) << 4));
        size_t go = (size_t)r * rowB + kb + (size_t)(c << 4);
        CP_ASYNC(dst, B + go, 16);
    }
}

template <int OP>  // 0 = up (sq_relu -> fp16 hi/lo), 1 = down (scale -> fp32)
__global__ void __launch_bounds__(NTHR, 1)
gemm_mma(const __half* __restrict__ Ahi_r, const __half* __restrict__ Alo_r,
         const __half* __restrict__ B_r,
         const __half* __restrict__ Ahi_s, const __half* __restrict__ Alo_s,
         const __half* __restrict__ B_s,
         __half* __restrict__ Ohi_r, __half* __restrict__ Olo_r,
         __half* __restrict__ Ohi_s, __half* __restrict__ Olo_s,
         float* __restrict__ Out_r, float* __restrict__ Out_s,
         int Klen, int Nlen) {
    int z = blockIdx.z;
    bool routed = (z < NEXP);
    int rows    = routed ? g_counts[z]  : NTOK;
    int rowBase = routed ? g_offsets[z] : 0;
    int rowTile = blockIdx.y * BM;
    if (rowTile >= rows) return;
    int colTile = blockIdx.x * BN;
    extern __shared__ char smem[];
    uint32_t sb = smem_u32(smem);
    int tid = threadIdx.x, wid = tid >> 5, lane = tid & 31;
    int rmax = rows - rowTile;

    const __half* Ahi = routed ? Ahi_r : Ahi_s;
    const __half* Alo = routed ? Alo_r : Alo_s;
    const __half* Bp  = routed ? (B_r + (size_t)z * Nlen * Klen) : B_s;

    const char* Ah = (const char*)(Ahi + (size_t)(rowBase + rowTile) * Klen);
    const char* Al = (const char*)(Alo + (size_t)(rowBase + rowTile) * Klen);
    const char* Bh = (const char*)(Bp + (size_t)colTile * Klen);
    size_t rowB = (size_t)Klen * 2;
    int nCh = Klen >> 6;

    // prologue: stages 0,1
    load_stage(sb,           Ah, Al, Bh, rowB, 0,   rmax, tid); CP_COMMIT();
    load_stage(sb + STAGE_B, Ah, Al, Bh, rowB, 128, rmax, tid); CP_COMMIT();

    int wm = (wid >> 2) << 5;  // 4 warp rows x 32
    int wn = (wid & 3) << 6;   // 4 warp cols x 64

    float acc[2][8][4];
#pragma unroll
    for (int a = 0; a < 2; a++)
#pragma unroll
        for (int b = 0; b < 8; b++)
#pragma unroll
            for (int c = 0; c < 4; c++) acc[a][b][c] = 0.f;

    for (int i = 0; i < nCh; i++) {
        CP_WAIT(1);
        __syncthreads();
        int nx = i + STAGES - 1;
        if (nx < nCh)
            load_stage(sb + (uint32_t)(nx % STAGES) * STAGE_B,
                       Ah, Al, Bh, rowB, (size_t)nx * 128, rmax, tid);
        CP_COMMIT();

        uint32_t st = sb + (uint32_t)(i % STAGES) * STAGE_B;
#pragma unroll
        for (int ks = 0; ks < 4; ks++) {
            uint32_t ah[2][4], al[2][4];
#pragma unroll
            for (int mt = 0; mt < 2; mt++) {
                int row = wm + (mt << 4) + (lane & 15);
                int ch  = (ks << 1) + (lane >> 4);
                uint32_t a = st + (uint32_t)(row * 128 + ((ch ^ (row & 7)) << 4));
                LDSM4(ah[mt], a);
                LDSM4(al[mt], a + TILE_B);
            }
            uint32_t bh[4][4];
#pragma unroll
            for (int g = 0; g < 4; g++) {
                int n  = wn + (g << 4) + ((lane >> 4) << 3) + (lane & 7);
                int ch = (ks << 1) + ((lane >> 3) & 1);
                uint32_t a = st + 2 * TILE_B + (uint32_t)(n * 128 + ((ch ^ (n & 7)) << 4));
                LDSM4(bh[g], a);
            }
#pragma unroll
            for (int mt = 0; mt < 2; mt++)
#pragma unroll
                for (int nt = 0; nt < 8; nt++) {
                    int g = nt >> 1, i0 = (nt & 1) << 1;
                    MMA16816(acc[mt][nt], ah[mt], bh[g][i0], bh[g][i0 + 1]);
                    MMA16816(acc[mt][nt], al[mt], bh[g][i0], bh[g][i0 + 1]);
                }
        }
    }

    // epilogue
#pragma unroll
    for (int mt = 0; mt < 2; mt++) {
#pragma unroll
        for (int half = 0; half < 2; half++) {
            int r = wm + (mt << 4) + (lane >> 2) + (half << 3);
            if (r < rmax) {
                size_t grow = (size_t)(rowBase + rowTile + r) * Nlen + colTile + wn;
                if (OP == 0) {
                    __half* Ohi = routed ? Ohi_r : Ohi_s;
                    __half* Olo = routed ? Olo_r : Olo_s;
#pragma unroll
                    for (int nt = 0; nt < 8; nt++) {
                        float f0 = acc[mt][nt][half * 2];
                        float f1 = acc[mt][nt][half * 2 + 1];
                        f0 = fmaxf(f0, 0.f); f0 *= f0;
                        f1 = fmaxf(f1, 0.f); f1 *= f1;
                        __half h0 = __float2half_rn(f0);
                        __half h1 = __float2half_rn(f1);
                        float l0 = f0 - __half2float(h0);
                        float l1 = f1 - __half2float(h1);
                        int col = (nt << 3) + ((lane & 3) << 1);
                        *(uint32_t*)(Ohi + grow + col) =
                            (uint32_t)__half_as_ushort(h0) |
                            ((uint32_t)__half_as_ushort(h1) << 16);
                        *(uint32_t*)(Olo + grow + col) = pack_half2(l0, l1);
                    }
                } else {
                    float* Out = routed ? Out_r : Out_s;
                    float scale = routed ? g_pair_prob[rowBase + rowTile + r] : 1.f;
#pragma unroll
                    for (int nt = 0; nt < 8; nt++) {
                        int col = (nt << 3) + ((lane & 3) << 1);
                        float2 v;
                        v.x = acc[mt][nt][half * 2]     * scale;
                        v.y = acc[mt][nt][half * 2 + 1] * scale;
                        *(float2*)(Out + grow + col) = v;
                    }
                }
            }
        }
    }
}

// out[token] += pair_out[pos0] + pair_out[pos1]
__global__ void combine_kernel(float* __restrict__ out) {
    int n = blockIdx.x;
    int d = threadIdx.x * 4;
    int p0 = g_pair_pos[2 * n];
    int p1 = g_pair_pos[2 * n + 1];
    float4 o = *(float4*)(out + (size_t)n * DIM + d);
    float4 a = *(const float4*)(g_pair_out + (size_t)p0 * DIM + d);
    float4 b = *(const float4*)(g_pair_out + (size_t)p1 * DIM + d);
    o.x += a.x + b.x; o.y += a.y + b.y; o.z += a.z + b.z; o.w += a.w + b.w;
    *(float4*)(out + (size_t)n * DIM + d) = o;
}

// ---------------- launch -----------------------------------------------------
extern "C" void kernel_launch(void* const* d_in, const int* in_sizes, int n_in,
                              void* d_out, int out_size) {
    const float* x   = (const float*)d_in[0];
    const float* Wr  = (const float*)d_in[1];
    const float* Wup = (const float*)d_in[2];
    const float* Wdn = (const float*)d_in[3];
    const float* Wsu = (const float*)d_in[4];
    const float* Wsd = (const float*)d_in[5];
    float* out = (float*)d_out;

    cudaFuncSetAttribute(gemm_mma<0>, cudaFuncAttributeMaxDynamicSharedMemorySize, GEMM_SMEM);
    cudaFuncSetAttribute(gemm_mma<1>, cudaFuncAttributeMaxDynamicSharedMemorySize, GEMM_SMEM);

    void* p;
    cudaGetSymbolAddress(&p, g_x_hi);   __half* x_hi  = (__half*)p;
    cudaGetSymbolAddress(&p, g_x_lo);   __half* x_lo  = (__half*)p;
    cudaGetSymbolAddress(&p, g_xg_hi);  __half* xg_hi = (__half*)p;
    cudaGetSymbolAddress(&p, g_xg_lo);  __half* xg_lo = (__half*)p;
    cudaGetSymbolAddress(&p, g_wupT);   __half* wupT  = (__half*)p;
    cudaGetSymbolAddress(&p, g_wdnT);   __half* wdnT  = (__half*)p;
    cudaGetSymbolAddress(&p, g_wsuT);   __half* wsuT  = (__half*)p;
    cudaGetSymbolAddress(&p, g_wsdT);   __half* wsdT  = (__half*)p;
    cudaGetSymbolAddress(&p, g_hsh_hi); __half* hsh_hi = (__half*)p;
    cudaGetSymbolAddress(&p, g_hsh_lo); __half* hsh_lo = (__half*)p;
    cudaGetSymbolAddress(&p, g_hrt_hi); __half* hrt_hi = (__half*)p;
    cudaGetSymbolAddress(&p, g_hrt_lo); __half* hrt_lo = (__half*)p;
    cudaGetSymbolAddress(&p, g_pair_out); float* pair_out = (float*)p;

    // routing
    zero_counts_kernel<<<1, 32>>>();
    router_kernel<<<NTOK / 4, 128>>>(x, Wr);
    prefix_kernel<<<1, 32>>>();
    scatter_kernel<<<NTOK / 256, 256>>>();

    // operand prep
    split_x_kernel<<<(NTOK * DIM) / (256 * 4), 256>>>(x);
    gather_x_kernel<<<NPAIR, 128>>>();
    {
        dim3 t(32, 8, 1);
        transpose_half_kernel<<<dim3(HDIM / 32, DIM / 32, NEXP), t>>>(Wup, wupT, DIM, HDIM);
        transpose_half_kernel<<<dim3(DIM / 32, HDIM / 32, NEXP), t>>>(Wdn, wdnT, HDIM, DIM);
        transpose_half_kernel<<<dim3(HDIM / 32, DIM / 32, 1), t>>>(Wsu, wsuT, DIM, HDIM);
        transpose_half_kernel<<<dim3(DIM / 32, HDIM / 32, 1), t>>>(Wsd, wsdT, HDIM, DIM);
    }

    // all UP GEMMs: z=0..7 routed (A=xg, B=wupT), z=8 shared (A=x, B=wsuT)
    gemm_mma<0><<<dim3(HDIM / BN, NPAIR / BM, NEXP + 1), NTHR, GEMM_SMEM>>>(
        xg_hi, xg_lo, wupT,
        x_hi, x_lo, wsuT,
        hrt_hi, hrt_lo, hsh_hi, hsh_lo, nullptr, nullptr,
        DIM, HDIM);

    // all DOWN GEMMs: routed -> pair_out, shared -> out
    gemm_mma<1><<<dim3(DIM / BN, NPAIR / BM, NEXP + 1), NTHR, GEMM_SMEM>>>(
        hrt_hi, hrt_lo, wdnT,
        hsh_hi, hsh_lo, wsdT,
        nullptr, nullptr, nullptr, nullptr, pair_out, out,
        HDIM, DIM);

    combine_kernel<<<NTOK, 256>>>(out);
}

// round 15
// speedup vs baseline: 1.4796x; 1.4796x over previous
#include <cuda_runtime.h>
#include <cuda_fp16.h>
#include <math.h>
#include <stdint.h>

#define NTOK 4096
#define DIM  1024
#define HDIM 4096
#define NEXP 8
#define NPAIR (NTOK * 2)

#define BM 128
#define BN 128
#define TILE_B 16384            // 128 rows x 128 bytes (64 fp16)
#define GEMM_SMEM 196608        // 192 KB (up: 4 stages x 48KB; down: 6 x 32KB)
#define NTHR 512

// ---------------- scratch (static device globals; no runtime allocation) ----
__device__ __half g_x_hi[(size_t)NTOK * DIM];
__device__ __half g_x_lo[(size_t)NTOK * DIM];
__device__ __half g_xg_hi[(size_t)NPAIR * DIM];
__device__ __half g_xg_lo[(size_t)NPAIR * DIM];
__device__ __half g_wupT[(size_t)NEXP * HDIM * DIM];  // [e][h][d] fp16
__device__ __half g_wdnT[(size_t)NEXP * DIM * HDIM];  // [e][d][h] fp16
__device__ __half g_wsuT[(size_t)HDIM * DIM];
__device__ __half g_wsdT[(size_t)DIM * HDIM];
__device__ __half g_hsh[(size_t)NTOK * HDIM];
__device__ __half g_hrt[(size_t)NPAIR * HDIM];
__device__ float g_pair_out[(size_t)NPAIR * DIM];
__device__ float g_pair_prob[NPAIR];
__device__ int   g_pair_token[NPAIR];
__device__ int   g_pair_pos[NPAIR];
__device__ int   g_topk_idx[NPAIR];
__device__ float g_topk_p[NPAIR];
__device__ int   g_counts[NEXP];
__device__ int   g_offsets[NEXP];
__device__ int   g_cursor[NEXP];

// ---------------- PTX helpers (sm_80-era only: valid on plain sm_103) -------
__device__ __forceinline__ uint32_t smem_u32(const void* p) {
    return (uint32_t)__cvta_generic_to_shared(p);
}
#define CP_ASYNC(dst, src, sz) \
    asm volatile("cp.async.cg.shared.global [%0], [%1], 16, %2;" \
                 :: "r"(dst), "l"(src), "r"(sz) : "memory")
#define CP_COMMIT() asm volatile("cp.async.commit_group;" ::: "memory")
#define CP_WAIT(n)  asm volatile("cp.async.wait_group %0;" :: "n"(n) : "memory")
#define LDSM4(r, a) \
    asm volatile("ldmatrix.sync.aligned.m8n8.x4.shared.b16 {%0,%1,%2,%3}, [%4];" \
                 : "=r"((r)[0]), "=r"((r)[1]), "=r"((r)[2]), "=r"((r)[3]) : "r"(a))
#define MMA16816(c, a, b0, b1) \
    asm volatile("mma.sync.aligned.m16n8k16.row.col.f32.f16.f16.f32 " \
                 "{%0,%1,%2,%3},{%4,%5,%6,%7},{%8,%9},{%0,%1,%2,%3};" \
                 : "+f"((c)[0]), "+f"((c)[1]), "+f"((c)[2]), "+f"((c)[3]) \
                 : "r"((a)[0]), "r"((a)[1]), "r"((a)[2]), "r"((a)[3]), \
                   "r"(b0), "r"(b1))

__device__ __forceinline__ uint32_t pack_half2(float a, float b) {
    __half h0 = __float2half_rn(a);
    __half h1 = __float2half_rn(b);
    return (uint32_t)__half_as_ushort(h0) | ((uint32_t)__half_as_ushort(h1) << 16);
}

// ---------------- tiny kernels ----------------------------------------------
__global__ void zero_counts_kernel() {
    if (threadIdx.x < NEXP) g_counts[threadIdx.x] = 0;
}

__global__ void router_kernel(const float* __restrict__ x,
                              const float* __restrict__ Wr) {
    int gw   = (blockIdx.x * blockDim.x + threadIdx.x) >> 5;
    int lane = threadIdx.x & 31;
    if (gw >= NTOK) return;
    const float* xr = x + (size_t)gw * DIM;
    float acc[NEXP];
#pragma unroll
    for (int e = 0; e < NEXP; e++) acc[e] = 0.f;
    for (int d = lane; d < DIM; d += 32) {
        float xv = xr[d];
        const float* w = Wr + (size_t)d * NEXP;
#pragma unroll
        for (int e = 0; e < NEXP; e++) acc[e] += xv * w[e];
    }
#pragma unroll
    for (int off = 16; off > 0; off >>= 1) {
#pragma unroll
        for (int e = 0; e < NEXP; e++)
            acc[e] += __shfl_xor_sync(0xffffffffu, acc[e], off);
    }
    if (lane == 0) {
        float p[NEXP];
#pragma unroll
        for (int e = 0; e < NEXP; e++) p[e] = 1.f / (1.f + expf(-acc[e]));
        float p1 = -1.f, p2 = -1.f; int i1 = 0, i2 = 0;
#pragma unroll
        for (int e = 0; e < NEXP; e++) {
            float v = p[e];
            if (v > p1)      { p2 = p1; i2 = i1; p1 = v; i1 = e; }
            else if (v > p2) { p2 = v;  i2 = e; }
        }
        float s = p1 + p2 + 1e-6f;
        p1 /= s; p2 /= s;
        g_topk_idx[2 * gw]     = i1;  g_topk_idx[2 * gw + 1] = i2;
        g_topk_p[2 * gw]       = p1;  g_topk_p[2 * gw + 1]   = p2;
        atomicAdd(&g_counts[i1], 1);
        atomicAdd(&g_counts[i2], 1);
    }
}

__global__ void prefix_kernel() {
    if (threadIdx.x == 0) {
        int s = 0;
        for (int e = 0; e < NEXP; e++) {
            g_offsets[e] = s; g_cursor[e] = s; s += g_counts[e];
        }
    }
}

__global__ void scatter_kernel() {
    int n = blockIdx.x * blockDim.x + threadIdx.x;
    if (n >= NTOK) return;
#pragma unroll
    for (int j = 0; j < 2; j++) {
        int e = g_topk_idx[2 * n + j];
        int pos = atomicAdd(&g_cursor[e], 1);
        g_pair_token[pos] = n;
        g_pair_prob[pos]  = g_topk_p[2 * n + j];
        g_pair_pos[2 * n + j] = pos;
    }
}

// split x -> fp16 hi/lo
__global__ void split_x_kernel(const float* __restrict__ x) {
    size_t i = ((size_t)blockIdx.x * blockDim.x + threadIdx.x) * 4;
    float4 v = *(const float4*)(x + i);
    float f[4] = {v.x, v.y, v.z, v.w};
    uint32_t hi[2], lo[2];
#pragma unroll
    for (int p = 0; p < 2; p++) {
        __half h0 = __float2half_rn(f[2 * p]);
        __half h1 = __float2half_rn(f[2 * p + 1]);
        float l0 = f[2 * p]     - __half2float(h0);
        float l1 = f[2 * p + 1] - __half2float(h1);
        hi[p] = (uint32_t)__half_as_ushort(h0) | ((uint32_t)__half_as_ushort(h1) << 16);
        lo[p] = pack_half2(l0, l1);
    }
    *(uint2*)(g_x_hi + i) = make_uint2(hi[0], hi[1]);
    *(uint2*)(g_x_lo + i) = make_uint2(lo[0], lo[1]);
}

__global__ void gather_x_kernel() {
    int pos = blockIdx.x;
    int tok = g_pair_token[pos];
    int d = threadIdx.x;  // 128 threads x 8 fp16
    ((uint4*)(g_xg_hi + (size_t)pos * DIM))[d] =
        ((const uint4*)(g_x_hi + (size_t)tok * DIM))[d];
    ((uint4*)(g_xg_lo + (size_t)pos * DIM))[d] =
        ((const uint4*)(g_x_lo + (size_t)tok * DIM))[d];
}

// transpose [R,C] fp32 -> [C,R] fp16  (blockIdx.z = expert slab)
__global__ void transpose_half_kernel(const float* __restrict__ src,
                                      __half* __restrict__ dst,
                                      int R, int C) {
    __shared__ float tile[32][33];
    size_t eo = (size_t)blockIdx.z * R * C;
    int c0 = blockIdx.x * 32, r0 = blockIdx.y * 32;
    int tx = threadIdx.x, ty = threadIdx.y;
#pragma unroll
    for (int i = 0; i < 4; i++)
        tile[ty + 8 * i][tx] = src[eo + (size_t)(r0 + ty + 8 * i) * C + c0 + tx];
    __syncthreads();
#pragma unroll
    for (int i = 0; i < 4; i++) {
        float v = tile[tx][ty + 8 * i];
        dst[eo + (size_t)(c0 + ty + 8 * i) * R + r0 + tx] = __float2half_rn(v);
    }
}

// ---------------- HMMA fp16 GEMM (128x128 tile, 16 warps 4x4, wtile 32x32) ---
// OP=0 (up):   A = x hi/lo (2 products), B = W fp16; epilogue sq_relu -> fp16
// OP=1 (down): A = h fp16 (1 product),   B = W fp16; epilogue scale -> fp32
// cp.async pipeline (up: 4 stages x 3 tiles; down: 6 stages x 2 tiles),
// XOR-swizzled smem, ldmatrix fragments.
// blockIdx.z: 0..NEXP-1 routed experts, NEXP = shared expert.

template <int NT>
__device__ __forceinline__ void load_stage(uint32_t sbase,
    const char* Ah, const char* Al, const char* B,
    size_t rowB, size_t kb, int rmax, int tid) {
#pragma unroll
    for (int t = 0; t < 2; t++) {
        int id = tid + t * NTHR;
        int r = id >> 3, c = id & 7;
        uint32_t dst = sbase + (uint32_t)(r * 128 + ((c ^ (r & 7)) << 4));
        size_t go = (size_t)r * rowB + kb + (size_t)(c << 4);
        int av = (r < rmax);
        size_t ga = av ? go : 0;
        int sz = av ? 16 : 0;
        CP_ASYNC(dst, Ah + ga, sz);
        if (NT == 3) CP_ASYNC(dst + TILE_B, Al + ga, sz);
        CP_ASYNC(dst + (NT - 1) * TILE_B, B + go, 16);
    }
}

template <int OP>  // 0 = up, 1 = down
__global__ void __launch_bounds__(NTHR, 1)
gemm_mma(const __half* __restrict__ Ahi_r, const __half* __restrict__ Alo_r,
         const __half* __restrict__ B_r,
         const __half* __restrict__ Ahi_s, const __half* __restrict__ Alo_s,
         const __half* __restrict__ B_s,
         __half* __restrict__ Oh_r, __half* __restrict__ Oh_s,
         float* __restrict__ Of_r, float* __restrict__ Of_s,
         int Klen, int Nlen) {
    constexpr int NT   = (OP == 0) ? 3 : 2;        // tiles per stage
    constexpr int NSTG = (OP == 0) ? 4 : 6;        // pipeline depth
    constexpr uint32_t STG_B = NT * TILE_B;

    int z = blockIdx.z;
    bool routed = (z < NEXP);
    int rows    = routed ? g_counts[z]  : NTOK;
    int rowBase = routed ? g_offsets[z] : 0;
    int rowTile = blockIdx.y * BM;
    if (rowTile >= rows) return;
    int colTile = blockIdx.x * BN;
    extern __shared__ char smem[];
    uint32_t sb = smem_u32(smem);
    int tid = threadIdx.x, wid = tid >> 5, lane = tid & 31;
    int rmax = rows - rowTile;

    const __half* Ahi = routed ? Ahi_r : Ahi_s;
    const __half* Alo = routed ? Alo_r : Alo_s;
    const __half* Bp  = routed ? (B_r + (size_t)z * Nlen * Klen) : B_s;

    const char* Ah = (const char*)(Ahi + (size_t)(rowBase + rowTile) * Klen);
    const char* Al = (const char*)(Alo + (size_t)(rowBase + rowTile) * Klen);
    const char* Bh = (const char*)(Bp + (size_t)colTile * Klen);
    size_t rowB = (size_t)Klen * 2;
    int nCh = Klen >> 6;

    // prologue: fill NSTG-1 stages
#pragma unroll
    for (int s = 0; s < NSTG - 1; s++) {
        if (s < nCh)
            load_stage<NT>(sb + s * STG_B, Ah, Al, Bh, rowB, (size_t)s * 128, rmax, tid);
        CP_COMMIT();
    }

    int wm = (wid >> 2) << 5;  // 4 warp rows x 32
    int wn = (wid & 3) << 5;   // 4 warp cols x 32

    float acc[2][4][4];
#pragma unroll
    for (int a = 0; a < 2; a++)
#pragma unroll
        for (int b = 0; b < 4; b++)
#pragma unroll
            for (int c = 0; c < 4; c++) acc[a][b][c] = 0.f;

    for (int i = 0; i < nCh; i++) {
        CP_WAIT(NSTG - 2);
        __syncthreads();
        int nx = i + NSTG - 1;
        if (nx < nCh)
            load_stage<NT>(sb + (uint32_t)(nx % NSTG) * STG_B,
                           Ah, Al, Bh, rowB, (size_t)nx * 128, rmax, tid);
        CP_COMMIT();

        uint32_t st = sb + (uint32_t)(i % NSTG) * STG_B;
#pragma unroll
        for (int ks = 0; ks < 4; ks++) {
            uint32_t ah[2][4], al[2][4];
#pragma unroll
            for (int mt = 0; mt < 2; mt++) {
                int row = wm + (mt << 4) + (lane & 15);
                int ch  = (ks << 1) + (lane >> 4);
                uint32_t a = st + (uint32_t)(row * 128 + ((ch ^ (row & 7)) << 4));
                LDSM4(ah[mt], a);
                if (OP == 0) LDSM4(al[mt], a + TILE_B);
            }
            uint32_t bh[2][4];
#pragma unroll
            for (int g = 0; g < 2; g++) {
                int n  = wn + (g << 4) + ((lane >> 4) << 3) + (lane & 7);
                int ch = (ks << 1) + ((lane >> 3) & 1);
                uint32_t a = st + (NT - 1) * TILE_B +
                             (uint32_t)(n * 128 + ((ch ^ (n & 7)) << 4));
                LDSM4(bh[g], a);
            }
#pragma unroll
            for (int mt = 0; mt < 2; mt++)
#pragma unroll
                for (int nt = 0; nt < 4; nt++) {
                    int g = nt >> 1, i0 = (nt & 1) << 1;
                    MMA16816(acc[mt][nt], ah[mt], bh[g][i0], bh[g][i0 + 1]);
                    if (OP == 0)
                        MMA16816(acc[mt][nt], al[mt], bh[g][i0], bh[g][i0 + 1]);
                }
        }
    }

    // epilogue
#pragma unroll
    for (int mt = 0; mt < 2; mt++) {
#pragma unroll
        for (int half = 0; half < 2; half++) {
            int r = wm + (mt << 4) + (lane >> 2) + (half << 3);
            if (r < rmax) {
                size_t grow = (size_t)(rowBase + rowTile + r) * Nlen + colTile + wn;
                if (OP == 0) {
                    __half* Oh = routed ? Oh_r : Oh_s;
#pragma unroll
                    for (int nt = 0; nt < 4; nt++) {
                        float f0 = acc[mt][nt][half * 2];
                        float f1 = acc[mt][nt][half * 2 + 1];
                        f0 = fmaxf(f0, 0.f); f0 *= f0;
                        f1 = fmaxf(f1, 0.f); f1 *= f1;
                        int col = (nt << 3) + ((lane & 3) << 1);
                        *(uint32_t*)(Oh + grow + col) = pack_half2(f0, f1);
                    }
                } else {
                    float* Of = routed ? Of_r : Of_s;
                    float scale = routed ? g_pair_prob[rowBase + rowTile + r] : 1.f;
#pragma unroll
                    for (int nt = 0; nt < 4; nt++) {
                        int col = (nt << 3) + ((lane & 3) << 1);
                        float2 v;
                        v.x = acc[mt][nt][half * 2]     * scale;
                        v.y = acc[mt][nt][half * 2 + 1] * scale;
                        *(float2*)(Of + grow + col) = v;
                    }
                }
            }
        }
    }
}

// out[token] += pair_out[pos0] + pair_out[pos1]
__global__ void combine_kernel(float* __restrict__ out) {
    int n = blockIdx.x;
    int d = threadIdx.x * 4;
    int p0 = g_pair_pos[2 * n];
    int p1 = g_pair_pos[2 * n + 1];
    float4 o = *(float4*)(out + (size_t)n * DIM + d);
    float4 a = *(const float4*)(g_pair_out + (size_t)p0 * DIM + d);
    float4 b = *(const float4*)(g_pair_out + (size_t)p1 * DIM + d);
    o.x += a.x + b.x; o.y += a.y + b.y; o.z += a.z + b.z; o.w += a.w + b.w;
    *(float4*)(out + (size_t)n * DIM + d) = o;
}

// ---------------- launch -----------------------------------------------------
extern "C" void kernel_launch(void* const* d_in, const int* in_sizes, int n_in,
                              void* d_out, int out_size) {
    const float* x   = (const float*)d_in[0];
    const float* Wr  = (const float*)d_in[1];
    const float* Wup = (const float*)d_in[2];
    const float* Wdn = (const float*)d_in[3];
    const float* Wsu = (const float*)d_in[4];
    const float* Wsd = (const float*)d_in[5];
    float* out = (float*)d_out;

    cudaFuncSetAttribute(gemm_mma<0>, cudaFuncAttributeMaxDynamicSharedMemorySize, GEMM_SMEM);
    cudaFuncSetAttribute(gemm_mma<1>, cudaFuncAttributeMaxDynamicSharedMemorySize, GEMM_SMEM);

    void* p;
    cudaGetSymbolAddress(&p, g_x_hi);   __half* x_hi  = (__half*)p;
    cudaGetSymbolAddress(&p, g_x_lo);   __half* x_lo  = (__half*)p;
    cudaGetSymbolAddress(&p, g_xg_hi);  __half* xg_hi = (__half*)p;
    cudaGetSymbolAddress(&p, g_xg_lo);  __half* xg_lo = (__half*)p;
    cudaGetSymbolAddress(&p, g_wupT);   __half* wupT  = (__half*)p;
    cudaGetSymbolAddress(&p, g_wdnT);   __half* wdnT  = (__half*)p;
    cudaGetSymbolAddress(&p, g_wsuT);   __half* wsuT  = (__half*)p;
    cudaGetSymbolAddress(&p, g_wsdT);   __half* wsdT  = (__half*)p;
    cudaGetSymbolAddress(&p, g_hsh);    __half* hsh   = (__half*)p;
    cudaGetSymbolAddress(&p, g_hrt);    __half* hrt   = (__half*)p;
    cudaGetSymbolAddress(&p, g_pair_out); float* pair_out = (float*)p;

    // routing
    zero_counts_kernel<<<1, 32>>>();
    router_kernel<<<NTOK / 4, 128>>>(x, Wr);
    prefix_kernel<<<1, 32>>>();
    scatter_kernel<<<NTOK / 256, 256>>>();

    // operand prep
    split_x_kernel<<<(NTOK * DIM) / (256 * 4), 256>>>(x);
    gather_x_kernel<<<NPAIR, 128>>>();
    {
        dim3 t(32, 8, 1);
        transpose_half_kernel<<<dim3(HDIM / 32, DIM / 32, NEXP), t>>>(Wup, wupT, DIM, HDIM);
        transpose_half_kernel<<<dim3(DIM / 32, HDIM / 32, NEXP), t>>>(Wdn, wdnT, HDIM, DIM);
        transpose_half_kernel<<<dim3(HDIM / 32, DIM / 32, 1), t>>>(Wsu, wsuT, DIM, HDIM);
        transpose_half_kernel<<<dim3(DIM / 32, HDIM / 32, 1), t>>>(Wsd, wsdT, HDIM, DIM);
    }

    // all UP GEMMs: z=0..7 routed (A=xg, B=wupT), z=8 shared (A=x, B=wsuT)
    gemm_mma<0><<<dim3(HDIM / BN, NPAIR / BM, NEXP + 1), NTHR, GEMM_SMEM>>>(
        xg_hi, xg_lo, wupT,
        x_hi, x_lo, wsuT,
        hrt, hsh, nullptr, nullptr,
        DIM, HDIM);

    // all DOWN GEMMs (single product): routed -> pair_out, shared -> out
    gemm_mma<1><<<dim3(DIM / BN, NPAIR / BM, NEXP + 1), NTHR, GEMM_SMEM>>>(
        hrt, nullptr, wdnT,
        hsh, nullptr, wsdT,
        nullptr, nullptr, pair_out, out,
        HDIM, DIM);

    combine_kernel<<<NTOK, 256>>>(out);
}

// round 16
// speedup vs baseline: 1.8096x; 1.2231x over previous
#include <cuda_runtime.h>
#include <cuda_fp16.h>
#include <math.h>
#include <stdint.h>

#define NTOK 4096
#define DIM  1024
#define HDIM 4096
#define NEXP 8
#define NPAIR (NTOK * 2)

#define BM 128
#define BN 128
#define TILE_B 16384            // 128 rows x 128 bytes (64 fp16)
#define NSTG 6
#define STG_B (2 * TILE_B)      // A, B tiles = 32 KB
#define GEMM_SMEM (NSTG * STG_B)  // 192 KB
#define NTHR 512

// ---------------- scratch (static device globals; no runtime allocation) ----
__device__ __half g_x16[(size_t)NTOK * DIM];
__device__ __half g_xg[(size_t)NPAIR * DIM];
__device__ __half g_wupT[(size_t)NEXP * HDIM * DIM];  // [e][h][d] fp16
__device__ __half g_wdnT[(size_t)NEXP * DIM * HDIM];  // [e][d][h] fp16
__device__ __half g_wsuT[(size_t)HDIM * DIM];
__device__ __half g_wsdT[(size_t)DIM * HDIM];
__device__ __half g_hsh[(size_t)NTOK * HDIM];
__device__ __half g_hrt[(size_t)NPAIR * HDIM];
__device__ float g_pair_out[(size_t)NPAIR * DIM];
__device__ float g_pair_prob[NPAIR];
__device__ int   g_pair_token[NPAIR];
__device__ int   g_pair_pos[NPAIR];
__device__ int   g_topk_idx[NPAIR];
__device__ float g_topk_p[NPAIR];
__device__ int   g_counts[NEXP];
__device__ int   g_offsets[NEXP];
__device__ int   g_cursor[NEXP];

// ---------------- PTX helpers (sm_80-era only: valid on plain sm_103) -------
__device__ __forceinline__ uint32_t smem_u32(const void* p) {
    return (uint32_t)__cvta_generic_to_shared(p);
}
#define CP_ASYNC(dst, src, sz) \
    asm volatile("cp.async.cg.shared.global [%0], [%1], 16, %2;" \
                 :: "r"(dst), "l"(src), "r"(sz) : "memory")
#define CP_COMMIT() asm volatile("cp.async.commit_group;" ::: "memory")
#define CP_WAIT(n)  asm volatile("cp.async.wait_group %0;" :: "n"(n) : "memory")
#define LDSM4(r, a) \
    asm volatile("ldmatrix.sync.aligned.m8n8.x4.shared.b16 {%0,%1,%2,%3}, [%4];" \
                 : "=r"((r)[0]), "=r"((r)[1]), "=r"((r)[2]), "=r"((r)[3]) : "r"(a))
#define MMA16816(c, a, b0, b1) \
    asm volatile("mma.sync.aligned.m16n8k16.row.col.f32.f16.f16.f32 " \
                 "{%0,%1,%2,%3},{%4,%5,%6,%7},{%8,%9},{%0,%1,%2,%3};" \
                 : "+f"((c)[0]), "+f"((c)[1]), "+f"((c)[2]), "+f"((c)[3]) \
                 : "r"((a)[0]), "r"((a)[1]), "r"((a)[2]), "r"((a)[3]), \
                   "r"(b0), "r"(b1))

__device__ __forceinline__ uint32_t pack_half2(float a, float b) {
    __half h0 = __float2half_rn(a);
    __half h1 = __float2half_rn(b);
    return (uint32_t)__half_as_ushort(h0) | ((uint32_t)__half_as_ushort(h1) << 16);
}

// ---------------- tiny kernels ----------------------------------------------
__global__ void zero_counts_kernel() {
    if (threadIdx.x < NEXP) g_counts[threadIdx.x] = 0;
}

__global__ void router_kernel(const float* __restrict__ x,
                              const float* __restrict__ Wr) {
    int gw   = (blockIdx.x * blockDim.x + threadIdx.x) >> 5;
    int lane = threadIdx.x & 31;
    if (gw >= NTOK) return;
    const float* xr = x + (size_t)gw * DIM;
    float acc[NEXP];
#pragma unroll
    for (int e = 0; e < NEXP; e++) acc[e] = 0.f;
    for (int d = lane; d < DIM; d += 32) {
        float xv = xr[d];
        const float* w = Wr + (size_t)d * NEXP;
#pragma unroll
        for (int e = 0; e < NEXP; e++) acc[e] += xv * w[e];
    }
#pragma unroll
    for (int off = 16; off > 0; off >>= 1) {
#pragma unroll
        for (int e = 0; e < NEXP; e++)
            acc[e] += __shfl_xor_sync(0xffffffffu, acc[e], off);
    }
    if (lane == 0) {
        float p[NEXP];
#pragma unroll
        for (int e = 0; e < NEXP; e++) p[e] = 1.f / (1.f + expf(-acc[e]));
        float p1 = -1.f, p2 = -1.f; int i1 = 0, i2 = 0;
#pragma unroll
        for (int e = 0; e < NEXP; e++) {
            float v = p[e];
            if (v > p1)      { p2 = p1; i2 = i1; p1 = v; i1 = e; }
            else if (v > p2) { p2 = v;  i2 = e; }
        }
        float s = p1 + p2 + 1e-6f;
        p1 /= s; p2 /= s;
        g_topk_idx[2 * gw]     = i1;  g_topk_idx[2 * gw + 1] = i2;
        g_topk_p[2 * gw]       = p1;  g_topk_p[2 * gw + 1]   = p2;
        atomicAdd(&g_counts[i1], 1);
        atomicAdd(&g_counts[i2], 1);
    }
}

__global__ void prefix_kernel() {
    if (threadIdx.x == 0) {
        int s = 0;
        for (int e = 0; e < NEXP; e++) {
            g_offsets[e] = s; g_cursor[e] = s; s += g_counts[e];
        }
    }
}

__global__ void scatter_kernel() {
    int n = blockIdx.x * blockDim.x + threadIdx.x;
    if (n >= NTOK) return;
#pragma unroll
    for (int j = 0; j < 2; j++) {
        int e = g_topk_idx[2 * n + j];
        int pos = atomicAdd(&g_cursor[e], 1);
        g_pair_token[pos] = n;
        g_pair_prob[pos]  = g_topk_p[2 * n + j];
        g_pair_pos[2 * n + j] = pos;
    }
}

// convert x -> fp16
__global__ void convert_x_kernel(const float* __restrict__ x) {
    size_t i = ((size_t)blockIdx.x * blockDim.x + threadIdx.x) * 4;
    float4 v = *(const float4*)(x + i);
    uint32_t a = pack_half2(v.x, v.y);
    uint32_t b = pack_half2(v.z, v.w);
    *(uint2*)(g_x16 + i) = make_uint2(a, b);
}

__global__ void gather_x_kernel() {
    int pos = blockIdx.x;
    int tok = g_pair_token[pos];
    int d = threadIdx.x;  // 128 threads x 8 fp16
    ((uint4*)(g_xg + (size_t)pos * DIM))[d] =
        ((const uint4*)(g_x16 + (size_t)tok * DIM))[d];
}

// transpose [R,C] fp32 -> [C,R] fp16  (blockIdx.z = expert slab)
__global__ void transpose_half_kernel(const float* __restrict__ src,
                                      __half* __restrict__ dst,
                                      int R, int C) {
    __shared__ float tile[32][33];
    size_t eo = (size_t)blockIdx.z * R * C;
    int c0 = blockIdx.x * 32, r0 = blockIdx.y * 32;
    int tx = threadIdx.x, ty = threadIdx.y;
#pragma unroll
    for (int i = 0; i < 4; i++)
        tile[ty + 8 * i][tx] = src[eo + (size_t)(r0 + ty + 8 * i) * C + c0 + tx];
    __syncthreads();
#pragma unroll
    for (int i = 0; i < 4; i++) {
        float v = tile[tx][ty + 8 * i];
        dst[eo + (size_t)(c0 + ty + 8 * i) * R + r0 + tx] = __float2half_rn(v);
    }
}

// ---------------- HMMA fp16 GEMM (128x128 tile, 16 warps 4x4, wtile 32x32) ---
// Single-product fp16 A@B^T, fp32 accumulate. 6-stage cp.async pipeline,
// XOR-swizzled smem, ldmatrix fragments.
// OP=0 (up): epilogue sq_relu -> fp16.  OP=1 (down): epilogue scale -> fp32.
// blockIdx.z: 0..NEXP-1 routed experts, NEXP = shared expert.

__device__ __forceinline__ void load_stage(uint32_t sbase,
    const char* A, const char* B,
    size_t rowB, size_t kb, int rmax, int tid) {
#pragma unroll
    for (int t = 0; t < 2; t++) {
        int id = tid + t * NTHR;
        int r = id >> 3, c = id & 7;
        uint32_t dst = sbase + (uint32_t)(r * 128 + ((c ^ (r & 7)) << 4));
        size_t go = (size_t)r * rowB + kb + (size_t)(c << 4);
        int av = (r < rmax);
        size_t ga = av ? go : 0;
        int sz = av ? 16 : 0;
        CP_ASYNC(dst,          A + ga, sz);
        CP_ASYNC(dst + TILE_B, B + go, 16);
    }
}

template <int OP>  // 0 = up, 1 = down
__global__ void __launch_bounds__(NTHR, 1)
gemm_mma(const __half* __restrict__ A_r, const __half* __restrict__ B_r,
         const __half* __restrict__ A_s, const __half* __restrict__ B_s,
         __half* __restrict__ Oh_r, __half* __restrict__ Oh_s,
         float* __restrict__ Of_r, float* __restrict__ Of_s,
         int Klen, int Nlen) {
    int z = blockIdx.z;
    bool routed = (z < NEXP);
    int rows    = routed ? g_counts[z]  : NTOK;
    int rowBase = routed ? g_offsets[z] : 0;
    int rowTile = blockIdx.y * BM;
    if (rowTile >= rows) return;
    int colTile = blockIdx.x * BN;
    extern __shared__ char smem[];
    uint32_t sb = smem_u32(smem);
    int tid = threadIdx.x, wid = tid >> 5, lane = tid & 31;
    int rmax = rows - rowTile;

    const __half* Ap = routed ? A_r : A_s;
    const __half* Bp = routed ? (B_r + (size_t)z * Nlen * Klen) : B_s;

    const char* A = (const char*)(Ap + (size_t)(rowBase + rowTile) * Klen);
    const char* B = (const char*)(Bp + (size_t)colTile * Klen);
    size_t rowB = (size_t)Klen * 2;
    int nCh = Klen >> 6;

    // prologue: fill NSTG-1 stages
#pragma unroll
    for (int s = 0; s < NSTG - 1; s++) {
        if (s < nCh)
            load_stage(sb + s * STG_B, A, B, rowB, (size_t)s * 128, rmax, tid);
        CP_COMMIT();
    }

    int wm = (wid >> 2) << 5;  // 4 warp rows x 32
    int wn = (wid & 3) << 5;   // 4 warp cols x 32

    float acc[2][4][4];
#pragma unroll
    for (int a = 0; a < 2; a++)
#pragma unroll
        for (int b = 0; b < 4; b++)
#pragma unroll
            for (int c = 0; c < 4; c++) acc[a][b][c] = 0.f;

    for (int i = 0; i < nCh; i++) {
        CP_WAIT(NSTG - 2);
        __syncthreads();
        int nx = i + NSTG - 1;
        if (nx < nCh)
            load_stage(sb + (uint32_t)(nx % NSTG) * STG_B,
                       A, B, rowB, (size_t)nx * 128, rmax, tid);
        CP_COMMIT();

        uint32_t st = sb + (uint32_t)(i % NSTG) * STG_B;
#pragma unroll
        for (int ks = 0; ks < 4; ks++) {
            uint32_t ah[2][4];
#pragma unroll
            for (int mt = 0; mt < 2; mt++) {
                int row = wm + (mt << 4) + (lane & 15);
                int ch  = (ks << 1) + (lane >> 4);
                uint32_t a = st + (uint32_t)(row * 128 + ((ch ^ (row & 7)) << 4));
                LDSM4(ah[mt], a);
            }
            uint32_t bh[2][4];
#pragma unroll
            for (int g = 0; g < 2; g++) {
                int n  = wn + (g << 4) + ((lane >> 4) << 3) + (lane & 7);
                int ch = (ks << 1) + ((lane >> 3) & 1);
                uint32_t a = st + TILE_B + (uint32_t)(n * 128 + ((ch ^ (n & 7)) << 4));
                LDSM4(bh[g], a);
            }
#pragma unroll
            for (int mt = 0; mt < 2; mt++)
#pragma unroll
                for (int nt = 0; nt < 4; nt++) {
                    int g = nt >> 1, i0 = (nt & 1) << 1;
                    MMA16816(acc[mt][nt], ah[mt], bh[g][i0], bh[g][i0 + 1]);
                }
        }
    }

    // epilogue
#pragma unroll
    for (int mt = 0; mt < 2; mt++) {
#pragma unroll
        for (int half = 0; half < 2; half++) {
            int r = wm + (mt << 4) + (lane >> 2) + (half << 3);
            if (r < rmax) {
                size_t grow = (size_t)(rowBase + rowTile + r) * Nlen + colTile + wn;
                if (OP == 0) {
                    __half* Oh = routed ? Oh_r : Oh_s;
#pragma unroll
                    for (int nt = 0; nt < 4; nt++) {
                        float f0 = acc[mt][nt][half * 2];
                        float f1 = acc[mt][nt][half * 2 + 1];
                        f0 = fmaxf(f0, 0.f); f0 *= f0;
                        f1 = fmaxf(f1, 0.f); f1 *= f1;
                        int col = (nt << 3) + ((lane & 3) << 1);
                        *(uint32_t*)(Oh + grow + col) = pack_half2(f0, f1);
                    }
                } else {
                    float* Of = routed ? Of_r : Of_s;
                    float scale = routed ? g_pair_prob[rowBase + rowTile + r] : 1.f;
#pragma unroll
                    for (int nt = 0; nt < 4; nt++) {
                        int col = (nt << 3) + ((lane & 3) << 1);
                        float2 v;
                        v.x = acc[mt][nt][half * 2]     * scale;
                        v.y = acc[mt][nt][half * 2 + 1] * scale;
                        *(float2*)(Of + grow + col) = v;
                    }
                }
            }
        }
    }
}

// out[token] += pair_out[pos0] + pair_out[pos1]
__global__ void combine_kernel(float* __restrict__ out) {
    int n = blockIdx.x;
    int d = threadIdx.x * 4;
    int p0 = g_pair_pos[2 * n];
    int p1 = g_pair_pos[2 * n + 1];
    float4 o = *(float4*)(out + (size_t)n * DIM + d);
    float4 a = *(const float4*)(g_pair_out + (size_t)p0 * DIM + d);
    float4 b = *(const float4*)(g_pair_out + (size_t)p1 * DIM + d);
    o.x += a.x + b.x; o.y += a.y + b.y; o.z += a.z + b.z; o.w += a.w + b.w;
    *(float4*)(out + (size_t)n * DIM + d) = o;
}

// ---------------- launch -----------------------------------------------------
extern "C" void kernel_launch(void* const* d_in, const int* in_sizes, int n_in,
                              void* d_out, int out_size) {
    const float* x   = (const float*)d_in[0];
    const float* Wr  = (const float*)d_in[1];
    const float* Wup = (const float*)d_in[2];
    const float* Wdn = (const float*)d_in[3];
    const float* Wsu = (const float*)d_in[4];
    const float* Wsd = (const float*)d_in[5];
    float* out = (float*)d_out;

    cudaFuncSetAttribute(gemm_mma<0>, cudaFuncAttributeMaxDynamicSharedMemorySize, GEMM_SMEM);
    cudaFuncSetAttribute(gemm_mma<1>, cudaFuncAttributeMaxDynamicSharedMemorySize, GEMM_SMEM);

    void* p;
    cudaGetSymbolAddress(&p, g_x16);   __half* x16  = (__half*)p;
    cudaGetSymbolAddress(&p, g_xg);    __half* xg   = (__half*)p;
    cudaGetSymbolAddress(&p, g_wupT);  __half* wupT = (__half*)p;
    cudaGetSymbolAddress(&p, g_wdnT);  __half* wdnT = (__half*)p;
    cudaGetSymbolAddress(&p, g_wsuT);  __half* wsuT = (__half*)p;
    cudaGetSymbolAddress(&p, g_wsdT);  __half* wsdT = (__half*)p;
    cudaGetSymbolAddress(&p, g_hsh);   __half* hsh  = (__half*)p;
    cudaGetSymbolAddress(&p, g_hrt);   __half* hrt  = (__half*)p;
    cudaGetSymbolAddress(&p, g_pair_out); float* pair_out = (float*)p;

    // routing
    zero_counts_kernel<<<1, 32>>>();
    router_kernel<<<NTOK / 4, 128>>>(x, Wr);
    prefix_kernel<<<1, 32>>>();
    scatter_kernel<<<NTOK / 256, 256>>>();

    // operand prep
    convert_x_kernel<<<(NTOK * DIM) / (256 * 4), 256>>>(x);
    gather_x_kernel<<<NPAIR, 128>>>();
    {
        dim3 t(32, 8, 1);
        transpose_half_kernel<<<dim3(HDIM / 32, DIM / 32, NEXP), t>>>(Wup, wupT, DIM, HDIM);
        transpose_half_kernel<<<dim3(DIM / 32, HDIM / 32, NEXP), t>>>(Wdn, wdnT, HDIM, DIM);
        transpose_half_kernel<<<dim3(HDIM / 32, DIM / 32, 1), t>>>(Wsu, wsuT, DIM, HDIM);
        transpose_half_kernel<<<dim3(DIM / 32, HDIM / 32, 1), t>>>(Wsd, wsdT, HDIM, DIM);
    }

    // all UP GEMMs: z=0..7 routed (A=xg, B=wupT), z=8 shared (A=x16, B=wsuT)
    gemm_mma<0><<<dim3(HDIM / BN, NPAIR / BM, NEXP + 1), NTHR, GEMM_SMEM>>>(
        xg, wupT, x16, wsuT,
        hrt, hsh, nullptr, nullptr,
        DIM, HDIM);

    // all DOWN GEMMs: routed -> pair_out, shared -> out
    gemm_mma<1><<<dim3(DIM / BN, NPAIR / BM, NEXP + 1), NTHR, GEMM_SMEM>>>(
        hrt, wdnT, hsh, wsdT,
        nullptr, nullptr, pair_out, out,
        HDIM, DIM);

    combine_kernel<<<NTOK, 256>>>(out);
}

// round 17
// speedup vs baseline: 2.0911x; 1.1555x over previous
#include <cuda_runtime.h>
#include <cuda_fp16.h>
#include <math.h>
#include <stdint.h>

#define NTOK 4096
#define DIM  1024
#define HDIM 4096
#define NEXP 8
#define NPAIR (NTOK * 2)

#define BM 64
#define BN 128
#define ATILE_B 8192            // 64 rows x 128 bytes
#define BTILE_B 16384           // 128 rows x 128 bytes
#define NSTG 4
#define STG_B (ATILE_B + BTILE_B)   // 24 KB
#define GEMM_SMEM (NSTG * STG_B)    // 96 KB -> 2 CTAs/SM
#define NTHR 256

// ---------------- scratch (static device globals; no runtime allocation) ----
__device__ __half g_x16[(size_t)NTOK * DIM];
__device__ __half g_xg[(size_t)NPAIR * DIM];
__device__ __half g_wupT[(size_t)NEXP * HDIM * DIM];  // [e][h][d] fp16
__device__ __half g_wdnT[(size_t)NEXP * DIM * HDIM];  // [e][d][h] fp16
__device__ __half g_wsuT[(size_t)HDIM * DIM];
__device__ __half g_wsdT[(size_t)DIM * HDIM];
__device__ __half g_hsh[(size_t)NTOK * HDIM];
__device__ __half g_hrt[(size_t)NPAIR * HDIM];
__device__ float g_pair_out[(size_t)NPAIR * DIM];
__device__ float g_pair_prob[NPAIR];
__device__ int   g_pair_token[NPAIR];
__device__ int   g_pair_pos[NPAIR];
__device__ int   g_topk_idx[NPAIR];
__device__ float g_topk_p[NPAIR];
__device__ int   g_counts[NEXP];
__device__ int   g_offsets[NEXP];
__device__ int   g_cursor[NEXP];

// ---------------- PTX helpers (sm_80-era only: valid on plain sm_103) -------
__device__ __forceinline__ uint32_t smem_u32(const void* p) {
    return (uint32_t)__cvta_generic_to_shared(p);
}
#define CP_ASYNC(dst, src, sz) \
    asm volatile("cp.async.cg.shared.global [%0], [%1], 16, %2;" \
                 :: "r"(dst), "l"(src), "r"(sz) : "memory")
#define CP_COMMIT() asm volatile("cp.async.commit_group;" ::: "memory")
#define CP_WAIT(n)  asm volatile("cp.async.wait_group %0;" :: "n"(n) : "memory")
#define LDSM4(r, a) \
    asm volatile("ldmatrix.sync.aligned.m8n8.x4.shared.b16 {%0,%1,%2,%3}, [%4];" \
                 : "=r"((r)[0]), "=r"((r)[1]), "=r"((r)[2]), "=r"((r)[3]) : "r"(a))
#define MMA16816(c, a, b0, b1) \
    asm volatile("mma.sync.aligned.m16n8k16.row.col.f32.f16.f16.f32 " \
                 "{%0,%1,%2,%3},{%4,%5,%6,%7},{%8,%9},{%0,%1,%2,%3};" \
                 : "+f"((c)[0]), "+f"((c)[1]), "+f"((c)[2]), "+f"((c)[3]) \
                 : "r"((a)[0]), "r"((a)[1]), "r"((a)[2]), "r"((a)[3]), \
                   "r"(b0), "r"(b1))

__device__ __forceinline__ uint32_t pack_half2(float a, float b) {
    __half h0 = __float2half_rn(a);
    __half h1 = __float2half_rn(b);
    return (uint32_t)__half_as_ushort(h0) | ((uint32_t)__half_as_ushort(h1) << 16);
}

// ---------------- tiny kernels ----------------------------------------------
__global__ void zero_counts_kernel() {
    if (threadIdx.x < NEXP) g_counts[threadIdx.x] = 0;
}

__global__ void router_kernel(const float* __restrict__ x,
                              const float* __restrict__ Wr) {
    int gw   = (blockIdx.x * blockDim.x + threadIdx.x) >> 5;
    int lane = threadIdx.x & 31;
    if (gw >= NTOK) return;
    const float* xr = x + (size_t)gw * DIM;
    float acc[NEXP];
#pragma unroll
    for (int e = 0; e < NEXP; e++) acc[e] = 0.f;
    for (int d = lane; d < DIM; d += 32) {
        float xv = xr[d];
        const float* w = Wr + (size_t)d * NEXP;
#pragma unroll
        for (int e = 0; e < NEXP; e++) acc[e] += xv * w[e];
    }
#pragma unroll
    for (int off = 16; off > 0; off >>= 1) {
#pragma unroll
        for (int e = 0; e < NEXP; e++)
            acc[e] += __shfl_xor_sync(0xffffffffu, acc[e], off);
    }
    if (lane == 0) {
        float p[NEXP];
#pragma unroll
        for (int e = 0; e < NEXP; e++) p[e] = 1.f / (1.f + expf(-acc[e]));
        float p1 = -1.f, p2 = -1.f; int i1 = 0, i2 = 0;
#pragma unroll
        for (int e = 0; e < NEXP; e++) {
            float v = p[e];
            if (v > p1)      { p2 = p1; i2 = i1; p1 = v; i1 = e; }
            else if (v > p2) { p2 = v;  i2 = e; }
        }
        float s = p1 + p2 + 1e-6f;
        p1 /= s; p2 /= s;
        g_topk_idx[2 * gw]     = i1;  g_topk_idx[2 * gw + 1] = i2;
        g_topk_p[2 * gw]       = p1;  g_topk_p[2 * gw + 1]   = p2;
        atomicAdd(&g_counts[i1], 1);
        atomicAdd(&g_counts[i2], 1);
    }
}

__global__ void prefix_kernel() {
    if (threadIdx.x == 0) {
        int s = 0;
        for (int e = 0; e < NEXP; e++) {
            g_offsets[e] = s; g_cursor[e] = s; s += g_counts[e];
        }
    }
}

__global__ void scatter_kernel() {
    int n = blockIdx.x * blockDim.x + threadIdx.x;
    if (n >= NTOK) return;
#pragma unroll
    for (int j = 0; j < 2; j++) {
        int e = g_topk_idx[2 * n + j];
        int pos = atomicAdd(&g_cursor[e], 1);
        g_pair_token[pos] = n;
        g_pair_prob[pos]  = g_topk_p[2 * n + j];
        g_pair_pos[2 * n + j] = pos;
    }
}

// convert x -> fp16
__global__ void convert_x_kernel(const float* __restrict__ x) {
    size_t i = ((size_t)blockIdx.x * blockDim.x + threadIdx.x) * 4;
    float4 v = *(const float4*)(x + i);
    uint32_t a = pack_half2(v.x, v.y);
    uint32_t b = pack_half2(v.z, v.w);
    *(uint2*)(g_x16 + i) = make_uint2(a, b);
}

__global__ void gather_x_kernel() {
    int pos = blockIdx.x;
    int tok = g_pair_token[pos];
    int d = threadIdx.x;  // 128 threads x 8 fp16
    ((uint4*)(g_xg + (size_t)pos * DIM))[d] =
        ((const uint4*)(g_x16 + (size_t)tok * DIM))[d];
}

// transpose [R,C] fp32 -> [C,R] fp16  (blockIdx.z = expert slab)
__global__ void transpose_half_kernel(const float* __restrict__ src,
                                      __half* __restrict__ dst,
                                      int R, int C) {
    __shared__ float tile[32][33];
    size_t eo = (size_t)blockIdx.z * R * C;
    int c0 = blockIdx.x * 32, r0 = blockIdx.y * 32;
    int tx = threadIdx.x, ty = threadIdx.y;
#pragma unroll
    for (int i = 0; i < 4; i++)
        tile[ty + 8 * i][tx] = src[eo + (size_t)(r0 + ty + 8 * i) * C + c0 + tx];
    __syncthreads();
#pragma unroll
    for (int i = 0; i < 4; i++) {
        float v = tile[tx][ty + 8 * i];
        dst[eo + (size_t)(c0 + ty + 8 * i) * R + r0 + tx] = __float2half_rn(v);
    }
}

// ---------------- HMMA fp16 GEMM (64x128 tile, 8 warps 2x4, wtile 32x32) -----
// Single-product fp16 A@B^T, fp32 accumulate. 4-stage cp.async pipeline,
// 96 KB smem -> 2 CTAs/SM (independent barrier domains overlap bubbles).
// OP=0 (up): epilogue sq_relu -> fp16.  OP=1 (down): epilogue scale -> fp32.
// blockIdx.z: 0..NEXP-1 routed experts, NEXP = shared expert.

__device__ __forceinline__ void load_stage(uint32_t sbase,
    const char* A, const char* B,
    size_t rowB, size_t kb, int rmax, int tid) {
    // A tile: 64 rows x 8 chunks = 512 cps
#pragma unroll
    for (int t = 0; t < 2; t++) {
        int id = tid + t * NTHR;
        int r = id >> 3, c = id & 7;
        uint32_t dst = sbase + (uint32_t)(r * 128 + ((c ^ (r & 7)) << 4));
        size_t go = (size_t)r * rowB + kb + (size_t)(c << 4);
        int av = (r < rmax);
        size_t ga = av ? go : 0;
        int sz = av ? 16 : 0;
        CP_ASYNC(dst, A + ga, sz);
    }
    // B tile: 128 rows x 8 chunks = 1024 cps
#pragma unroll
    for (int t = 0; t < 4; t++) {
        int id = tid + t * NTHR;
        int r = id >> 3, c = id & 7;
        uint32_t dst = sbase + ATILE_B + (uint32_t)(r * 128 + ((c ^ (r & 7)) << 4));
        size_t go = (size_t)r * rowB + kb + (size_t)(c << 4);
        CP_ASYNC(dst, B + go, 16);
    }
}

template <int OP>  // 0 = up, 1 = down
__global__ void __launch_bounds__(NTHR, 2)
gemm_mma(const __half* __restrict__ A_r, const __half* __restrict__ B_r,
         const __half* __restrict__ A_s, const __half* __restrict__ B_s,
         __half* __restrict__ Oh_r, __half* __restrict__ Oh_s,
         float* __restrict__ Of_r, float* __restrict__ Of_s,
         int Klen, int Nlen) {
    int z = blockIdx.z;
    bool routed = (z < NEXP);
    int rows    = routed ? g_counts[z]  : NTOK;
    int rowBase = routed ? g_offsets[z] : 0;
    int rowTile = blockIdx.y * BM;
    if (rowTile >= rows) return;
    int colTile = blockIdx.x * BN;
    extern __shared__ char smem[];
    uint32_t sb = smem_u32(smem);
    int tid = threadIdx.x, wid = tid >> 5, lane = tid & 31;
    int rmax = rows - rowTile;

    const __half* Ap = routed ? A_r : A_s;
    const __half* Bp = routed ? (B_r + (size_t)z * Nlen * Klen) : B_s;

    const char* A = (const char*)(Ap + (size_t)(rowBase + rowTile) * Klen);
    const char* B = (const char*)(Bp + (size_t)colTile * Klen);
    size_t rowB = (size_t)Klen * 2;
    int nCh = Klen >> 6;

    // prologue: fill NSTG-1 stages
#pragma unroll
    for (int s = 0; s < NSTG - 1; s++) {
        if (s < nCh)
            load_stage(sb + s * STG_B, A, B, rowB, (size_t)s * 128, rmax, tid);
        CP_COMMIT();
    }

    int wm = (wid >> 2) << 5;  // 2 warp rows x 32
    int wn = (wid & 3) << 5;   // 4 warp cols x 32

    float acc[2][4][4];
#pragma unroll
    for (int a = 0; a < 2; a++)
#pragma unroll
        for (int b = 0; b < 4; b++)
#pragma unroll
            for (int c = 0; c < 4; c++) acc[a][b][c] = 0.f;

    for (int i = 0; i < nCh; i++) {
        CP_WAIT(NSTG - 2);
        __syncthreads();
        int nx = i + NSTG - 1;
        if (nx < nCh)
            load_stage(sb + (uint32_t)(nx % NSTG) * STG_B,
                       A, B, rowB, (size_t)nx * 128, rmax, tid);
        CP_COMMIT();

        uint32_t st = sb + (uint32_t)(i % NSTG) * STG_B;
#pragma unroll
        for (int ks = 0; ks < 4; ks++) {
            uint32_t ah[2][4];
#pragma unroll
            for (int mt = 0; mt < 2; mt++) {
                int row = wm + (mt << 4) + (lane & 15);
                int ch  = (ks << 1) + (lane >> 4);
                uint32_t a = st + (uint32_t)(row * 128 + ((ch ^ (row & 7)) << 4));
                LDSM4(ah[mt], a);
            }
            uint32_t bh[2][4];
#pragma unroll
            for (int g = 0; g < 2; g++) {
                int n  = wn + (g << 4) + ((lane >> 4) << 3) + (lane & 7);
                int ch = (ks << 1) + ((lane >> 3) & 1);
                uint32_t a = st + ATILE_B + (uint32_t)(n * 128 + ((ch ^ (n & 7)) << 4));
                LDSM4(bh[g], a);
            }
#pragma unroll
            for (int mt = 0; mt < 2; mt++)
#pragma unroll
                for (int nt = 0; nt < 4; nt++) {
                    int g = nt >> 1, i0 = (nt & 1) << 1;
                    MMA16816(acc[mt][nt], ah[mt], bh[g][i0], bh[g][i0 + 1]);
                }
        }
    }

    // epilogue
#pragma unroll
    for (int mt = 0; mt < 2; mt++) {
#pragma unroll
        for (int half = 0; half < 2; half++) {
            int r = wm + (mt << 4) + (lane >> 2) + (half << 3);
            if (r < rmax) {
                size_t grow = (size_t)(rowBase + rowTile + r) * Nlen + colTile + wn;
                if (OP == 0) {
                    __half* Oh = routed ? Oh_r : Oh_s;
#pragma unroll
                    for (int nt = 0; nt < 4; nt++) {
                        float f0 = acc[mt][nt][half * 2];
                        float f1 = acc[mt][nt][half * 2 + 1];
                        f0 = fmaxf(f0, 0.f); f0 *= f0;
                        f1 = fmaxf(f1, 0.f); f1 *= f1;
                        int col = (nt << 3) + ((lane & 3) << 1);
                        *(uint32_t*)(Oh + grow + col) = pack_half2(f0, f1);
                    }
                } else {
                    float* Of = routed ? Of_r : Of_s;
                    float scale = routed ? g_pair_prob[rowBase + rowTile + r] : 1.f;
#pragma unroll
                    for (int nt = 0; nt < 4; nt++) {
                        int col = (nt << 3) + ((lane & 3) << 1);
                        float2 v;
                        v.x = acc[mt][nt][half * 2]     * scale;
                        v.y = acc[mt][nt][half * 2 + 1] * scale;
                        *(float2*)(Of + grow + col) = v;
                    }
                }
            }
        }
    }
}

// out[token] += pair_out[pos0] + pair_out[pos1]
__global__ void combine_kernel(float* __restrict__ out) {
    int n = blockIdx.x;
    int d = threadIdx.x * 4;
    int p0 = g_pair_pos[2 * n];
    int p1 = g_pair_pos[2 * n + 1];
    float4 o = *(float4*)(out + (size_t)n * DIM + d);
    float4 a = *(const float4*)(g_pair_out + (size_t)p0 * DIM + d);
    float4 b = *(const float4*)(g_pair_out + (size_t)p1 * DIM + d);
    o.x += a.x + b.x; o.y += a.y + b.y; o.z += a.z + b.z; o.w += a.w + b.w;
    *(float4*)(out + (size_t)n * DIM + d) = o;
}

// ---------------- launch -----------------------------------------------------
extern "C" void kernel_launch(void* const* d_in, const int* in_sizes, int n_in,
                              void* d_out, int out_size) {
    const float* x   = (const float*)d_in[0];
    const float* Wr  = (const float*)d_in[1];
    const float* Wup = (const float*)d_in[2];
    const float* Wdn = (const float*)d_in[3];
    const float* Wsu = (const float*)d_in[4];
    const float* Wsd = (const float*)d_in[5];
    float* out = (float*)d_out;

    cudaFuncSetAttribute(gemm_mma<0>, cudaFuncAttributeMaxDynamicSharedMemorySize, GEMM_SMEM);
    cudaFuncSetAttribute(gemm_mma<1>, cudaFuncAttributeMaxDynamicSharedMemorySize, GEMM_SMEM);

    void* p;
    cudaGetSymbolAddress(&p, g_x16);   __half* x16  = (__half*)p;
    cudaGetSymbolAddress(&p, g_xg);    __half* xg   = (__half*)p;
    cudaGetSymbolAddress(&p, g_wupT);  __half* wupT = (__half*)p;
    cudaGetSymbolAddress(&p, g_wdnT);  __half* wdnT = (__half*)p;
    cudaGetSymbolAddress(&p, g_wsuT);  __half* wsuT = (__half*)p;
    cudaGetSymbolAddress(&p, g_wsdT);  __half* wsdT = (__half*)p;
    cudaGetSymbolAddress(&p, g_hsh);   __half* hsh  = (__half*)p;
    cudaGetSymbolAddress(&p, g_hrt);   __half* hrt  = (__half*)p;
    cudaGetSymbolAddress(&p, g_pair_out); float* pair_out = (float*)p;

    // routing
    zero_counts_kernel<<<1, 32>>>();
    router_kernel<<<NTOK / 4, 128>>>(x, Wr);
    prefix_kernel<<<1, 32>>>();
    scatter_kernel<<<NTOK / 256, 256>>>();

    // operand prep
    convert_x_kernel<<<(NTOK * DIM) / (256 * 4), 256>>>(x);
    gather_x_kernel<<<NPAIR, 128>>>();
    {
        dim3 t(32, 8, 1);
        transpose_half_kernel<<<dim3(HDIM / 32, DIM / 32, NEXP), t>>>(Wup, wupT, DIM, HDIM);
        transpose_half_kernel<<<dim3(DIM / 32, HDIM / 32, NEXP), t>>>(Wdn, wdnT, HDIM, DIM);
        transpose_half_kernel<<<dim3(HDIM / 32, DIM / 32, 1), t>>>(Wsu, wsuT, DIM, HDIM);
        transpose_half_kernel<<<dim3(DIM / 32, HDIM / 32, 1), t>>>(Wsd, wsdT, HDIM, DIM);
    }

    // all UP GEMMs: z=0..7 routed (A=xg, B=wupT), z=8 shared (A=x16, B=wsuT)
    gemm_mma<0><<<dim3(HDIM / BN, NPAIR / BM, NEXP + 1), NTHR, GEMM_SMEM>>>(
        xg, wupT, x16, wsuT,
        hrt, hsh, nullptr, nullptr,
        DIM, HDIM);

    // all DOWN GEMMs: routed -> pair_out, shared -> out
    gemm_mma<1><<<dim3(DIM / BN, NPAIR / BM, NEXP + 1), NTHR, GEMM_SMEM>>>(
        hrt, wdnT, hsh, wsdT,
        nullptr, nullptr, pair_out, out,
        HDIM, DIM);

    combine_kernel<<<NTOK, 256>>>(out);
}